// round 1
// baseline (speedup 1.0000x reference)
#include <cuda_runtime.h>

#define IMG_H 512
#define IMG_W 512

__global__ __launch_bounds__(256, 8)
void cheby_smooth_kernel(const float* __restrict__ x,
                         const float* __restrict__ f,
                         const float* __restrict__ kA,
                         float* __restrict__ out)
{
    const int b  = blockIdx.z;
    const int r  = blockIdx.y * 8 + threadIdx.y;            // output row
    const int c0 = (blockIdx.x * 32 + threadIdx.x) * 4;     // first of 4 output cols

    // Stage this batch's 3x3 kernel into smem (one broadcast load per block).
    __shared__ float k[9];
    if (threadIdx.y == 0 && threadIdx.x < 9)
        k[threadIdx.x] = kA[b * 9 + threadIdx.x];
    __syncthreads();

    const size_t base = (size_t)b * IMG_H * IMG_W;
    const float* __restrict__ xb = x + base;
    const float* __restrict__ fb = f + base;
    float* __restrict__ ob = out + base;

    float acc0 = 0.f, acc1 = 0.f, acc2 = 0.f, acc3 = 0.f;
    float4 xc = make_float4(0.f, 0.f, 0.f, 0.f);   // center-row values (always set at i==1)

    #pragma unroll
    for (int i = 0; i < 3; ++i) {
        const int rr = r - 1 + i;
        if (rr < 0 || rr >= IMG_H) continue;       // zero padding top/bottom
        const float* __restrict__ row = xb + (size_t)rr * IMG_W;

        const float4 mid = *reinterpret_cast<const float4*>(row + c0);
        const float  left  = (c0 > 0)           ? row[c0 - 1] : 0.f;
        const float  right = (c0 + 4 < IMG_W)   ? row[c0 + 4] : 0.f;
        if (i == 1) xc = mid;

        const float k0 = k[i * 3 + 0];
        const float k1 = k[i * 3 + 1];
        const float k2 = k[i * 3 + 2];

        acc0 = fmaf(left,  k0, fmaf(mid.x, k1, fmaf(mid.y, k2, acc0)));
        acc1 = fmaf(mid.x, k0, fmaf(mid.y, k1, fmaf(mid.z, k2, acc1)));
        acc2 = fmaf(mid.y, k0, fmaf(mid.z, k1, fmaf(mid.w, k2, acc2)));
        acc3 = fmaf(mid.z, k0, fmaf(mid.w, k1, fmaf(right, k2, acc3)));
    }

    const float4 fv = *reinterpret_cast<const float4*>(fb + (size_t)r * IMG_W + c0);
    const float inv6 = 1.0f / 6.0f;

    float4 o;
    o.x = xc.x + (fv.x - acc0) * inv6;
    o.y = xc.y + (fv.y - acc1) * inv6;
    o.z = xc.z + (fv.z - acc2) * inv6;
    o.w = xc.w + (fv.w - acc3) * inv6;

    *reinterpret_cast<float4*>(ob + (size_t)r * IMG_W + c0) = o;
}

extern "C" void kernel_launch(void* const* d_in, const int* in_sizes, int n_in,
                              void* d_out, int out_size)
{
    const float* x  = (const float*)d_in[0];   // [64,1,512,512]
    const float* f  = (const float*)d_in[1];   // [64,1,512,512]
    const float* kA = (const float*)d_in[2];   // [64,1,3,3]
    float* out = (float*)d_out;

    dim3 block(32, 8, 1);
    dim3 grid(IMG_W / (32 * 4), IMG_H / 8, 64); // (4, 64, 64)
    cheby_smooth_kernel<<<grid, block>>>(x, f, kA, out);
}

// round 2
// speedup vs baseline: 1.1024x; 1.1024x over previous
#include <cuda_runtime.h>

#define IMG_H 512
#define IMG_W 512

__global__ __launch_bounds__(256, 8)
void cheby_smooth_kernel(const float* __restrict__ x,
                         const float* __restrict__ f,
                         const float* __restrict__ kA,
                         float* __restrict__ out)
{
    const int b    = blockIdx.z;
    const int lane = threadIdx.x;                       // 0..31 == lane id (blockDim.x = 32)
    const int r0   = blockIdx.y * 16 + threadIdx.y * 2; // first of 2 output rows
    const int c0   = (blockIdx.x * 32 + lane) * 4;      // first of 4 output cols

    // Stage this batch's 3x3 kernel into smem (one broadcast load per block).
    __shared__ float k[9];
    if (threadIdx.y == 0 && lane < 9)
        k[lane] = kA[b * 9 + lane];
    __syncthreads();

    const size_t base = (size_t)b * IMG_H * IMG_W;
    const float* __restrict__ xb = x + base;
    const float* __restrict__ fb = f + base;
    float* __restrict__ ob = out + base;

    float a00 = 0.f, a01 = 0.f, a02 = 0.f, a03 = 0.f;   // Ax for row r0
    float a10 = 0.f, a11 = 0.f, a12 = 0.f, a13 = 0.f;   // Ax for row r0+1
    float4 xc0 = make_float4(0.f, 0.f, 0.f, 0.f);
    float4 xc1 = make_float4(0.f, 0.f, 0.f, 0.f);

    #pragma unroll
    for (int i = 0; i < 4; ++i) {
        const int rr = r0 - 1 + i;
        const bool valid = (rr >= 0) && (rr < IMG_H);
        const float* __restrict__ row = xb + (size_t)rr * IMG_W;

        float4 mid = make_float4(0.f, 0.f, 0.f, 0.f);
        if (valid)
            mid = *reinterpret_cast<const float4*>(row + c0);

        // Halo from neighboring lanes (entire warp shares the same rr).
        float left  = __shfl_up_sync(0xffffffffu, mid.w, 1);
        float right = __shfl_down_sync(0xffffffffu, mid.x, 1);
        if (lane == 0)
            left  = (valid && c0 > 0)           ? row[c0 - 1] : 0.f;
        if (lane == 31)
            right = (valid && c0 + 4 < IMG_W)   ? row[c0 + 4] : 0.f;

        if (i == 1) xc0 = mid;
        if (i == 2) xc1 = mid;

        if (i < 3) {  // contributes to output row r0 (kernel row i)
            const float k0 = k[i * 3 + 0];
            const float k1 = k[i * 3 + 1];
            const float k2 = k[i * 3 + 2];
            a00 = fmaf(left,  k0, fmaf(mid.x, k1, fmaf(mid.y, k2, a00)));
            a01 = fmaf(mid.x, k0, fmaf(mid.y, k1, fmaf(mid.z, k2, a01)));
            a02 = fmaf(mid.y, k0, fmaf(mid.z, k1, fmaf(mid.w, k2, a02)));
            a03 = fmaf(mid.z, k0, fmaf(mid.w, k1, fmaf(right, k2, a03)));
        }
        if (i > 0) {  // contributes to output row r0+1 (kernel row i-1)
            const float k0 = k[(i - 1) * 3 + 0];
            const float k1 = k[(i - 1) * 3 + 1];
            const float k2 = k[(i - 1) * 3 + 2];
            a10 = fmaf(left,  k0, fmaf(mid.x, k1, fmaf(mid.y, k2, a10)));
            a11 = fmaf(mid.x, k0, fmaf(mid.y, k1, fmaf(mid.z, k2, a11)));
            a12 = fmaf(mid.y, k0, fmaf(mid.z, k1, fmaf(mid.w, k2, a12)));
            a13 = fmaf(mid.z, k0, fmaf(mid.w, k1, fmaf(right, k2, a13)));
        }
    }

    const float inv6 = 1.0f / 6.0f;

    const float4 fv0 = *reinterpret_cast<const float4*>(fb + (size_t)r0 * IMG_W + c0);
    const float4 fv1 = *reinterpret_cast<const float4*>(fb + (size_t)(r0 + 1) * IMG_W + c0);

    float4 o0, o1;
    o0.x = xc0.x + (fv0.x - a00) * inv6;
    o0.y = xc0.y + (fv0.y - a01) * inv6;
    o0.z = xc0.z + (fv0.z - a02) * inv6;
    o0.w = xc0.w + (fv0.w - a03) * inv6;
    o1.x = xc1.x + (fv1.x - a10) * inv6;
    o1.y = xc1.y + (fv1.y - a11) * inv6;
    o1.z = xc1.z + (fv1.z - a12) * inv6;
    o1.w = xc1.w + (fv1.w - a13) * inv6;

    *reinterpret_cast<float4*>(ob + (size_t)r0 * IMG_W + c0)       = o0;
    *reinterpret_cast<float4*>(ob + (size_t)(r0 + 1) * IMG_W + c0) = o1;
}

extern "C" void kernel_launch(void* const* d_in, const int* in_sizes, int n_in,
                              void* d_out, int out_size)
{
    const float* x  = (const float*)d_in[0];   // [64,1,512,512]
    const float* f  = (const float*)d_in[1];   // [64,1,512,512]
    const float* kA = (const float*)d_in[2];   // [64,1,3,3]
    float* out = (float*)d_out;

    dim3 block(32, 8, 1);
    dim3 grid(IMG_W / (32 * 4), IMG_H / 16, 64); // (4, 32, 64)
    cheby_smooth_kernel<<<grid, block>>>(x, f, kA, out);
}

// round 3
// speedup vs baseline: 1.1835x; 1.0736x over previous
#include <cuda_runtime.h>

#define IMG_H 512
#define IMG_W 512

__global__ __launch_bounds__(256)
void cheby_smooth_kernel(const float* __restrict__ x,
                         const float* __restrict__ f,
                         const float* __restrict__ kA,
                         float* __restrict__ out)
{
    const int b    = blockIdx.z;
    const int lane = threadIdx.x;                       // blockDim.x == 32
    const int r0   = blockIdx.y * 32 + threadIdx.y * 4; // first of 4 output rows
    const int c0   = (blockIdx.x * 32 + lane) * 4;      // first of 4 output cols

    // Stage this batch's 3x3 kernel into smem (one broadcast load per block).
    __shared__ float k[9];
    if (threadIdx.y == 0 && lane < 9)
        k[lane] = kA[b * 9 + lane];
    __syncthreads();

    const size_t base = (size_t)b * IMG_H * IMG_W;
    const float* __restrict__ xb = x + base;
    const float* __restrict__ fb = f + base;
    float* __restrict__ ob = out + base;

    // ---- Phase 1: issue ALL global loads up front (max MLP) ----
    float4 mid[6];
    float  lf[6], rt[6];

    #pragma unroll
    for (int i = 0; i < 6; ++i) {
        const int rr = r0 - 1 + i;
        const bool valid = (rr >= 0) && (rr < IMG_H);
        const float* __restrict__ row = xb + (size_t)rr * IMG_W;
        mid[i] = valid ? *reinterpret_cast<const float4*>(row + c0)
                       : make_float4(0.f, 0.f, 0.f, 0.f);
        // Only lanes 0 / 31 need a real boundary element (predicated scalar LDG).
        lf[i] = (lane == 0  && valid && c0 > 0)           ? row[c0 - 1] : 0.f;
        rt[i] = (lane == 31 && valid && c0 + 4 < IMG_W)   ? row[c0 + 4] : 0.f;
    }

    float4 fv[4];
    #pragma unroll
    for (int j = 0; j < 4; ++j)
        fv[j] = *reinterpret_cast<const float4*>(fb + (size_t)(r0 + j) * IMG_W + c0);

    // ---- Phase 2: intra-warp halo exchange ----
    #pragma unroll
    for (int i = 0; i < 6; ++i) {
        const float l = __shfl_up_sync(0xffffffffu, mid[i].w, 1);
        const float r = __shfl_down_sync(0xffffffffu, mid[i].x, 1);
        if (lane != 0)  lf[i] = l;
        if (lane != 31) rt[i] = r;
    }

    // ---- Phase 3: compute 4 output rows ----
    const float inv6 = 1.0f / 6.0f;

    #pragma unroll
    for (int j = 0; j < 4; ++j) {
        float a0 = 0.f, a1 = 0.f, a2 = 0.f, a3 = 0.f;
        #pragma unroll
        for (int t = 0; t < 3; ++t) {
            const int i = j + t;
            const float k0 = k[t * 3 + 0];
            const float k1 = k[t * 3 + 1];
            const float k2 = k[t * 3 + 2];
            a0 = fmaf(lf[i],    k0, fmaf(mid[i].x, k1, fmaf(mid[i].y, k2, a0)));
            a1 = fmaf(mid[i].x, k0, fmaf(mid[i].y, k1, fmaf(mid[i].z, k2, a1)));
            a2 = fmaf(mid[i].y, k0, fmaf(mid[i].z, k1, fmaf(mid[i].w, k2, a2)));
            a3 = fmaf(mid[i].z, k0, fmaf(mid[i].w, k1, fmaf(rt[i],    k2, a3)));
        }
        const float4 xc = mid[j + 1];
        float4 o;
        o.x = xc.x + (fv[j].x - a0) * inv6;
        o.y = xc.y + (fv[j].y - a1) * inv6;
        o.z = xc.z + (fv[j].z - a2) * inv6;
        o.w = xc.w + (fv[j].w - a3) * inv6;
        *reinterpret_cast<float4*>(ob + (size_t)(r0 + j) * IMG_W + c0) = o;
    }
}

extern "C" void kernel_launch(void* const* d_in, const int* in_sizes, int n_in,
                              void* d_out, int out_size)
{
    const float* x  = (const float*)d_in[0];   // [64,1,512,512]
    const float* f  = (const float*)d_in[1];   // [64,1,512,512]
    const float* kA = (const float*)d_in[2];   // [64,1,3,3]
    float* out = (float*)d_out;

    dim3 block(32, 8, 1);
    dim3 grid(IMG_W / (32 * 4), IMG_H / 32, 64); // (4, 16, 64)
    cheby_smooth_kernel<<<grid, block>>>(x, f, kA, out);
}

// round 4
// speedup vs baseline: 1.2293x; 1.0387x over previous
#include <cuda_runtime.h>

#define IMG_H 512
#define IMG_W 512

__global__ __launch_bounds__(128)
void cheby_smooth_kernel(const float* __restrict__ x,
                         const float* __restrict__ f,
                         const float* __restrict__ kA,
                         float* __restrict__ out)
{
    const int b    = blockIdx.z;
    const int lane = threadIdx.x;                                 // blockDim.x == 32
    const int r0   = (blockIdx.y * 4 + threadIdx.y) * 8;          // first of 8 output rows
    const int c0   = (blockIdx.x * 32 + lane) * 4;                // first of 4 output cols

    // Stage this batch's 3x3 kernel into smem (one broadcast load per block).
    __shared__ float k[9];
    if (threadIdx.y == 0 && lane < 9)
        k[lane] = kA[b * 9 + lane];
    __syncthreads();

    const size_t base = (size_t)b * IMG_H * IMG_W;
    const float* __restrict__ xb = x + base;
    const float* __restrict__ fb = f + base;
    float* __restrict__ ob = out + base;

    // ---- Phase 1: issue ALL global loads up front (max MLP) ----
    float4 mid[10];
    float  lf[10], rt[10];

    #pragma unroll
    for (int i = 0; i < 10; ++i) {
        const int rr = r0 - 1 + i;
        const bool valid = (rr >= 0) && (rr < IMG_H);
        const float* __restrict__ row = xb + (size_t)rr * IMG_W;
        mid[i] = valid ? *reinterpret_cast<const float4*>(row + c0)
                       : make_float4(0.f, 0.f, 0.f, 0.f);
        // Only lanes 0 / 31 need a real boundary element (predicated scalar LDG).
        lf[i] = (lane == 0  && valid && c0 > 0)         ? row[c0 - 1] : 0.f;
        rt[i] = (lane == 31 && valid && c0 + 4 < IMG_W) ? row[c0 + 4] : 0.f;
    }

    float4 fv[8];
    #pragma unroll
    for (int j = 0; j < 8; ++j)
        fv[j] = *reinterpret_cast<const float4*>(fb + (size_t)(r0 + j) * IMG_W + c0);

    // ---- Phase 2: intra-warp halo exchange ----
    #pragma unroll
    for (int i = 0; i < 10; ++i) {
        const float l = __shfl_up_sync(0xffffffffu, mid[i].w, 1);
        const float r = __shfl_down_sync(0xffffffffu, mid[i].x, 1);
        if (lane != 0)  lf[i] = l;
        if (lane != 31) rt[i] = r;
    }

    // ---- Phase 3: compute 8 output rows ----
    const float inv6 = 1.0f / 6.0f;

    #pragma unroll
    for (int j = 0; j < 8; ++j) {
        float a0 = 0.f, a1 = 0.f, a2 = 0.f, a3 = 0.f;
        #pragma unroll
        for (int t = 0; t < 3; ++t) {
            const int i = j + t;
            const float k0 = k[t * 3 + 0];
            const float k1 = k[t * 3 + 1];
            const float k2 = k[t * 3 + 2];
            a0 = fmaf(lf[i],    k0, fmaf(mid[i].x, k1, fmaf(mid[i].y, k2, a0)));
            a1 = fmaf(mid[i].x, k0, fmaf(mid[i].y, k1, fmaf(mid[i].z, k2, a1)));
            a2 = fmaf(mid[i].y, k0, fmaf(mid[i].z, k1, fmaf(mid[i].w, k2, a2)));
            a3 = fmaf(mid[i].z, k0, fmaf(mid[i].w, k1, fmaf(rt[i],    k2, a3)));
        }
        const float4 xc = mid[j + 1];
        float4 o;
        o.x = xc.x + (fv[j].x - a0) * inv6;
        o.y = xc.y + (fv[j].y - a1) * inv6;
        o.z = xc.z + (fv[j].z - a2) * inv6;
        o.w = xc.w + (fv[j].w - a3) * inv6;
        *reinterpret_cast<float4*>(ob + (size_t)(r0 + j) * IMG_W + c0) = o;
    }
}

extern "C" void kernel_launch(void* const* d_in, const int* in_sizes, int n_in,
                              void* d_out, int out_size)
{
    const float* x  = (const float*)d_in[0];   // [64,1,512,512]
    const float* f  = (const float*)d_in[1];   // [64,1,512,512]
    const float* kA = (const float*)d_in[2];   // [64,1,3,3]
    float* out = (float*)d_out;

    dim3 block(32, 4, 1);
    dim3 grid(IMG_W / (32 * 4), IMG_H / (4 * 8), 64); // (4, 16, 64)
    cheby_smooth_kernel<<<grid, block>>>(x, f, kA, out);
}